// round 7
// baseline (speedup 1.0000x reference)
#include <cuda_runtime.h>
#include <cuda_bf16.h>
#include <cstdint>
#include <math.h>

// Problem constants
#define BB 4
#define SS 2048
#define DD 1024
#define HH 16
#define HD 64
#define MTOT (BB*SS)      // 8192
#define NQKV (3*DD)       // 3072
#define NHEADS (BB*HH)    // 64

// Q pre-scale: 1/sqrt(64) * log2(e)  (softmax done in exp2 domain)
#define QSCALE 0.1803368801111204f

// ---------------------------------------------------------------------------
// Scratch (static device globals — allowed)
// ---------------------------------------------------------------------------
__device__ __nv_bfloat16 g_Xh[(size_t)MTOT*DD];
__device__ __nv_bfloat16 g_Xl[(size_t)MTOT*DD];
__device__ __nv_bfloat16 g_WqTh[(size_t)NQKV*DD];
__device__ __nv_bfloat16 g_WqTl[(size_t)NQKV*DD];
__device__ __nv_bfloat16 g_WoTh[(size_t)DD*DD];
__device__ __nv_bfloat16 g_WoTl[(size_t)DD*DD];
__device__ __nv_bfloat16 g_Qh[(size_t)NHEADS*SS*HD];
__device__ __nv_bfloat16 g_Ql[(size_t)NHEADS*SS*HD];
__device__ __nv_bfloat16 g_Kh[(size_t)NHEADS*SS*HD];
__device__ __nv_bfloat16 g_Kl[(size_t)NHEADS*SS*HD];
__device__ __nv_bfloat16 g_Vh[(size_t)NHEADS*SS*HD];
__device__ __nv_bfloat16 g_Vl[(size_t)NHEADS*SS*HD];
__device__ __nv_bfloat16 g_Oh[(size_t)MTOT*DD];
__device__ __nv_bfloat16 g_Ol[(size_t)MTOT*DD];

// ---------------------------------------------------------------------------
// PTX helpers (plain compute_103-compatible: mma.sync / ldmatrix / cp.async)
// ---------------------------------------------------------------------------
__device__ __forceinline__ uint32_t smem_u32(const void* p) {
    uint32_t a;
    asm("{ .reg .u64 t; cvta.to.shared.u64 t, %1; cvt.u32.u64 %0, t; }"
        : "=r"(a) : "l"(p));
    return a;
}
__device__ __forceinline__ void cp16(uint32_t dst, const void* src) {
    asm volatile("cp.async.cg.shared.global [%0], [%1], 16;\n"
                 :: "r"(dst), "l"(src));
}
#define CP_COMMIT() asm volatile("cp.async.commit_group;\n" ::: "memory")
#define CP_WAIT(n)  asm volatile("cp.async.wait_group %0;\n" :: "n"(n) : "memory")

__device__ __forceinline__ void ldsm4(uint32_t* r, uint32_t addr) {
    asm volatile("ldmatrix.sync.aligned.m8n8.x4.shared.b16 {%0,%1,%2,%3}, [%4];\n"
                 : "=r"(r[0]), "=r"(r[1]), "=r"(r[2]), "=r"(r[3]) : "r"(addr));
}
__device__ __forceinline__ void ldsm4t(uint32_t* r, uint32_t addr) {
    asm volatile("ldmatrix.sync.aligned.m8n8.x4.trans.shared.b16 {%0,%1,%2,%3}, [%4];\n"
                 : "=r"(r[0]), "=r"(r[1]), "=r"(r[2]), "=r"(r[3]) : "r"(addr));
}
__device__ __forceinline__ void mma_bf16(float* c, const uint32_t* a,
                                         uint32_t b0, uint32_t b1) {
    asm volatile(
        "mma.sync.aligned.m16n8k16.row.col.f32.bf16.bf16.f32 "
        "{%0,%1,%2,%3}, {%4,%5,%6,%7}, {%8,%9}, {%0,%1,%2,%3};\n"
        : "+f"(c[0]), "+f"(c[1]), "+f"(c[2]), "+f"(c[3])
        : "r"(a[0]), "r"(a[1]), "r"(a[2]), "r"(a[3]), "r"(b0), "r"(b1));
}
__device__ __forceinline__ float ex2(float x) {
    float y;
    asm("ex2.approx.ftz.f32 %0, %1;" : "=f"(y) : "f"(x));
    return y;
}
__device__ __forceinline__ void split2(float x, float y,
                                       __nv_bfloat162& h2, __nv_bfloat162& l2) {
    __nv_bfloat16 hx = __float2bfloat16(x);
    __nv_bfloat16 hy = __float2bfloat16(y);
    h2.x = hx; h2.y = hy;
    l2.x = __float2bfloat16(x - __bfloat162float(hx));
    l2.y = __float2bfloat16(y - __bfloat162float(hy));
}

// ---------------------------------------------------------------------------
// Prep: split x into bf16 hi/lo
// ---------------------------------------------------------------------------
__global__ void __launch_bounds__(256) split_x_kernel(const float* __restrict__ x)
{
    size_t i4 = ((size_t)blockIdx.x * 256 + threadIdx.x) * 4;
    float4 v = *(const float4*)(x + i4);
    __nv_bfloat162 h0, l0, h1, l1;
    split2(v.x, v.y, h0, l0);
    split2(v.z, v.w, h1, l1);
    *(__nv_bfloat162*)(g_Xh + i4)     = h0;
    *(__nv_bfloat162*)(g_Xh + i4 + 2) = h1;
    *(__nv_bfloat162*)(g_Xl + i4)     = l0;
    *(__nv_bfloat162*)(g_Xl + i4 + 2) = l1;
}

// Prep: transpose W [K][N] -> T[n][k] bf16 hi/lo
__global__ void __launch_bounds__(256) transpose_split_kernel(
    const float* __restrict__ W, int K, int N,
    __nv_bfloat16* __restrict__ Th, __nv_bfloat16* __restrict__ Tl)
{
    __shared__ float t[32][33];
    int nb = blockIdx.x * 32, kb = blockIdx.y * 32;
    int tx = threadIdx.x, ty = threadIdx.y;
    #pragma unroll
    for (int j = 0; j < 4; j++)
        t[ty + j*8][tx] = W[(size_t)(kb + ty + j*8) * N + nb + tx];
    __syncthreads();
    #pragma unroll
    for (int j = 0; j < 4; j++) {
        int n = nb + ty + j*8;
        float v = t[tx][ty + j*8];
        __nv_bfloat16 h = __float2bfloat16(v);
        Th[(size_t)n * K + kb + tx] = h;
        Tl[(size_t)n * K + kb + tx] = __float2bfloat16(v - __bfloat162float(h));
    }
}

// ---------------------------------------------------------------------------
// Extended-K bf16 GEMM (3-pass split as K=3072):
//   C[M][N] = sum_p  Ap . Bp^T   with A pattern [h|l|h], B pattern [h|h|l]
// BM=BN=256, BK=32, 512 threads, 16 warps (4m x 4n), warp tile 64x64,
// 3-stage cp.async (120KB smem), 1 CTA/SM (16 warps).
// 16 LDSM per warp per chunk for 128K MACs = 16 MAC/byte smem.
// ---------------------------------------------------------------------------
#define GPITCH 80
#define GSTG (256*GPITCH)   // 20480 per operand per stage
#define SMEM_GEMM (6*GSTG)  // 122880

__global__ void __launch_bounds__(512, 1) gemm_ext_kernel(
    const __nv_bfloat16* __restrict__ Ah, const __nv_bfloat16* __restrict__ Al,
    const __nv_bfloat16* __restrict__ Bh, const __nv_bfloat16* __restrict__ Bl,
    const float* __restrict__ bias, float* __restrict__ out, int mode)
{
    extern __shared__ char sm[];
    const uint32_t sb = smem_u32(sm);
    const int tid = threadIdx.x, wid = tid >> 5, lane = tid & 31;
    const int wm = wid >> 2, wn = wid & 3;   // 4 x 4 warp grid
    const int m0 = blockIdx.y * 256, n0 = blockIdx.x * 256;

    float acc[4][8][4];
    #pragma unroll
    for (int i = 0; i < 4; i++)
        #pragma unroll
        for (int j = 0; j < 8; j++)
            #pragma unroll
            for (int e = 0; e < 4; e++) acc[i][j][e] = 0.0f;

    // issue one 32-K chunk into stage st (0..2): 2 A + 2 B cp16 per thread
    #define GEMM_ISSUE(c, st) do {                                             \
        int _p = (c) >> 5; int _kb = ((c) & 31) * 32;                          \
        const __nv_bfloat16* _Ap = (_p == 1) ? Al : Ah;                        \
        const __nv_bfloat16* _Bp = (_p == 2) ? Bl : Bh;                        \
        uint32_t _da = sb + (st) * GSTG;                                       \
        uint32_t _db = sb + 3*GSTG + (st) * GSTG;                              \
        _Pragma("unroll")                                                      \
        for (int _j = 0; _j < 2; _j++) {                                       \
            int _idx = tid + _j*512;                                           \
            int _row = _idx >> 2, _q = _idx & 3;                               \
            cp16(_da + _row*GPITCH + _q*16,                                    \
                 _Ap + (size_t)(m0+_row)*DD + _kb + _q*8);                     \
            cp16(_db + _row*GPITCH + _q*16,                                    \
                 _Bp + (size_t)(n0+_row)*DD + _kb + _q*8);                     \
        }                                                                      \
    } while (0)

    GEMM_ISSUE(0, 0); CP_COMMIT();
    GEMM_ISSUE(1, 1); CP_COMMIT();

    const int NCH = 96;  // 3072 / 32
    int cur = 0;         // stage of chunk c
    for (int c = 0; c < NCH; c++) {
        CP_WAIT(1);
        __syncthreads();
        int nxt = cur + 2 >= 3 ? cur - 1 : cur + 2;
        if (c + 2 < NCH) GEMM_ISSUE(c + 2, nxt);
        CP_COMMIT();

        uint32_t da = sb + cur * GSTG;
        uint32_t db = sb + 3*GSTG + cur * GSTG;

        // B fragments: 8 x (n8 x k32)
        uint32_t bfr[8][4];
        #pragma unroll
        for (int nt = 0; nt < 8; nt++)
            ldsm4(bfr[nt], db + (wn*64 + nt*8 + (lane & 7))*GPITCH + (lane >> 3)*16);

        #pragma unroll
        for (int kk = 0; kk < 2; kk++) {
            uint32_t afr[4][4];
            #pragma unroll
            for (int mt = 0; mt < 4; mt++)
                ldsm4(afr[mt], da + (wm*64 + mt*16 + (lane & 15))*GPITCH
                               + kk*32 + (lane >> 4)*16);
            #pragma unroll
            for (int mt = 0; mt < 4; mt++)
                #pragma unroll
                for (int nt = 0; nt < 8; nt++)
                    mma_bf16(acc[mt][nt], afr[mt], bfr[nt][kk*2], bfr[nt][kk*2+1]);
        }
        cur = cur + 1 >= 3 ? 0 : cur + 1;
    }

    // ---- epilogue ----
    #pragma unroll
    for (int mt = 0; mt < 4; mt++) {
        #pragma unroll
        for (int rr = 0; rr < 2; rr++) {
            int row = wm*64 + mt*16 + (lane >> 2) + rr*8;
            int m = m0 + row;
            #pragma unroll
            for (int nt = 0; nt < 8; nt++) {
                int col = n0 + wn*64 + nt*8 + 2*(lane & 3);
                float v0 = acc[mt][nt][rr*2]   + bias[col];
                float v1 = acc[mt][nt][rr*2+1] + bias[col+1];
                if (mode == 1) {
                    float2 f2; f2.x = v0; f2.y = v1;
                    *(float2*)&out[(size_t)m*DD + col] = f2;
                } else {
                    int h = col / 192;
                    int t = col - h*192;
                    int which = t >> 6;
                    int hd = t & 63;
                    if (which == 0) { v0 *= QSCALE; v1 *= QSCALE; }
                    __nv_bfloat162 h2, l2;
                    split2(v0, v1, h2, l2);
                    int b = m >> 11, s = m & 2047;
                    size_t off = (((size_t)b*HH + h)*SS + s)*HD + hd;
                    __nv_bfloat16* dh = (which == 0) ? g_Qh : (which == 1) ? g_Kh : g_Vh;
                    __nv_bfloat16* dl = (which == 0) ? g_Ql : (which == 1) ? g_Kl : g_Vl;
                    *(__nv_bfloat162*)(dh + off) = h2;
                    *(__nv_bfloat162*)(dl + off) = l2;
                }
            }
        }
    }
}

// ---------------------------------------------------------------------------
// Flash attention via mma.sync, 3-pass split, physical hi/lo dedup (as R6).
// ---------------------------------------------------------------------------
#define QPITCH 272
#define VPITCH 144
#define QS_OFF 0
#define KS_OFF 17408                 // Q: 64*272
#define KBUF   17408                 // K buf: 64*272
#define VS_OFF (KS_OFF + 2*KBUF)     // 52224
#define VBUF   18432                 // V buf: 128*144
#define PS_OFF (VS_OFF + 2*VBUF)     // 89088
#define RED_OFF (PS_OFF + 17408)     // 106496
#define SMEM_ATTN (RED_OFF + 1024)   // 107520

__global__ void __launch_bounds__(256, 2) attn_kernel()
{
    const int qt = blockIdx.x;   // 0..31
    const int bh = blockIdx.y;   // 0..63
    extern __shared__ char sm[];
    const uint32_t sb = smem_u32(sm);
    const int tid = threadIdx.x, wid = tid >> 5, lane = tid & 31;
    const int wm = wid >> 1, wn = wid & 1;

    const size_t base = (size_t)bh * SS * HD;
    const __nv_bfloat16* Qh = g_Qh + base + (size_t)qt*64*HD;
    const __nv_bfloat16* Ql = g_Ql + base + (size_t)qt*64*HD;
    const __nv_bfloat16* Kh = g_Kh + base;
    const __nv_bfloat16* Kl = g_Kl + base;
    const __nv_bfloat16* Vh = g_Vh + base;
    const __nv_bfloat16* Vl = g_Vl + base;

    // ---- load Q: phys [Qh(128B) | Ql(128B)] per row ----
    #pragma unroll
    for (int j = 0; j < 4; j++) {
        int idx = tid + j*256;
        int row = idx >> 4, q = idx & 15;
        if (q < 8)
            cp16(sb + QS_OFF + row*QPITCH + q*16, Qh + (size_t)row*HD + q*8);
        else
            cp16(sb + QS_OFF + row*QPITCH + 128 + (q-8)*16, Ql + (size_t)row*HD + (q-8)*8);
    }

    // K/V tile loader: K phys [Kh|Kl] 272B pitch; V phys [Vh rows 0-63; Vl rows 64-127]
    #define LOAD_KV(t, buf) do {                                               \
        int _s0 = (t) * 64;                                                    \
        _Pragma("unroll")                                                      \
        for (int j = 0; j < 4; j++) {                                          \
            int _idx = tid + j*256;                                            \
            int _row = _idx >> 4, _q = _idx & 15;                              \
            if (_q < 8)                                                        \
                cp16(sb + KS_OFF + (buf)*KBUF + _row*QPITCH + _q*16,           \
                     Kh + (size_t)(_s0 + _row)*HD + _q*8);                     \
            else                                                               \
                cp16(sb + KS_OFF + (buf)*KBUF + _row*QPITCH + 128 + (_q-8)*16, \
                     Kl + (size_t)(_s0 + _row)*HD + (_q-8)*8);                 \
        }                                                                      \
        _Pragma("unroll")                                                      \
        for (int j = 0; j < 4; j++) {                                          \
            int _idx = tid + j*256;                                            \
            int _vr = _idx >> 3, _q = _idx & 7;                                \
            const __nv_bfloat16* _src = (_vr < 64)                             \
                ? Vh + (size_t)(_s0 + _vr)*HD + _q*8                           \
                : Vl + (size_t)(_s0 + _vr - 64)*HD + _q*8;                     \
            cp16(sb + VS_OFF + (buf)*VBUF + _vr*VPITCH + _q*16, _src);         \
        }                                                                      \
    } while (0)

    LOAD_KV(0, 0);
    CP_COMMIT();

    float oacc[4][4];
    #pragma unroll
    for (int j = 0; j < 4; j++)
        #pragma unroll
        for (int e = 0; e < 4; e++) oacc[j][e] = 0.0f;
    float mst[2] = {-1e30f, -1e30f};
    float lst[2] = {0.0f, 0.0f};

    float* redm = (float*)(sm + RED_OFF);   // [2][64]
    float* reds = redm + 128;               // [2][64]
    const int rbase = wm*16 + (lane >> 2);

    // pass index maps (byte offsets within 272B rows); each kc = 32 ext-K
    const int qoff_tab[6] = {0, 64, 128, 192, 0, 64};     // Q: [h|l|h]
    const int koff_tab[6] = {0, 64, 0, 64, 128, 192};     // K: [h|h|l]

    for (int t = 0; t < 32; t++) {
        const int buf = t & 1;
        CP_WAIT(0);                            // tile t fully arrived
        __syncthreads();                       // + all warps past PV(t-1)
        if (t + 1 < 32) LOAD_KV(t + 1, buf ^ 1);
        CP_COMMIT();

        // ---- S = Q_ext . K_ext^T (64 x 64, ext K = 192) ----
        float sacc[4][4];
        #pragma unroll
        for (int j = 0; j < 4; j++)
            #pragma unroll
            for (int e = 0; e < 4; e++) sacc[j][e] = 0.0f;

        const uint32_t kb = sb + KS_OFF + buf*KBUF;
        #pragma unroll
        for (int kc = 0; kc < 6; kc++) {
            uint32_t bfr[4][4];
            #pragma unroll
            for (int nt = 0; nt < 4; nt++)
                ldsm4(bfr[nt], kb + (wn*32 + nt*8 + (lane & 7))*QPITCH
                               + koff_tab[kc] + (lane >> 3)*16);
            #pragma unroll
            for (int kk = 0; kk < 2; kk++) {
                uint32_t afr[4];
                ldsm4(afr, sb + QS_OFF + (wm*16 + (lane & 15))*QPITCH
                           + qoff_tab[kc] + kk*32 + (lane >> 4)*16);
                #pragma unroll
                for (int nt = 0; nt < 4; nt++)
                    mma_bf16(sacc[nt], afr, bfr[nt][kk*2], bfr[nt][kk*2+1]);
            }
        }

        // ---- online softmax (exp2 domain) ----
        #pragma unroll
        for (int rr = 0; rr < 2; rr++) {
            float mx = sacc[0][rr*2];
            #pragma unroll
            for (int nt = 0; nt < 4; nt++) {
                mx = fmaxf(mx, sacc[nt][rr*2]);
                mx = fmaxf(mx, sacc[nt][rr*2+1]);
            }
            mx = fmaxf(mx, __shfl_xor_sync(0xffffffffu, mx, 1));
            mx = fmaxf(mx, __shfl_xor_sync(0xffffffffu, mx, 2));
            if ((lane & 3) == 0)
                redm[wn*64 + rbase + rr*8] = mx;
        }
        __syncthreads();

        float alpha[2];
        #pragma unroll
        for (int rr = 0; rr < 2; rr++) {
            int row = rbase + rr*8;
            float rm = fmaxf(redm[row], redm[64 + row]);
            float mn = fmaxf(mst[rr], rm);
            alpha[rr] = ex2(mst[rr] - mn);
            mst[rr] = mn;
            float sum = 0.0f;
            #pragma unroll
            for (int nt = 0; nt < 4; nt++) {
                float p0 = ex2(sacc[nt][rr*2]   - mn);
                float p1 = ex2(sacc[nt][rr*2+1] - mn);
                sacc[nt][rr*2] = p0; sacc[nt][rr*2+1] = p1;
                sum += p0 + p1;
            }
            sum += __shfl_xor_sync(0xffffffffu, sum, 1);
            sum += __shfl_xor_sync(0xffffffffu, sum, 2);
            if ((lane & 3) == 0)
                reds[wn*64 + row] = sum;
        }

        // write P phys [Ph(128B) | Pl(128B)]
        #pragma unroll
        for (int rr = 0; rr < 2; rr++) {
            int row = rbase + rr*8;
            char* prow = sm + PS_OFF + row*QPITCH;
            #pragma unroll
            for (int nt = 0; nt < 4; nt++) {
                int klc = wn*32 + nt*8 + 2*(lane & 3);
                __nv_bfloat162 h2, l2;
                split2(sacc[nt][rr*2], sacc[nt][rr*2+1], h2, l2);
                *(__nv_bfloat162*)(prow + klc*2)       = h2;
                *(__nv_bfloat162*)(prow + 128 + klc*2) = l2;
            }
        }
        __syncthreads();

        // l update + O rescale
        #pragma unroll
        for (int rr = 0; rr < 2; rr++) {
            int row = rbase + rr*8;
            lst[rr] = lst[rr]*alpha[rr] + reds[row] + reds[64+row];
            #pragma unroll
            for (int nt = 0; nt < 4; nt++) {
                oacc[nt][rr*2]   *= alpha[rr];
                oacc[nt][rr*2+1] *= alpha[rr];
            }
        }

        // ---- O += P_ext . V_ext (ext K = 192 over keys) ----
        // passes: k16 0-3: Ph.Vh | 4-7: Pl.Vh | 8-11: Ph.Vl
        const uint32_t vb = sb + VS_OFF + buf*VBUF;
        #pragma unroll
        for (int k16 = 0; k16 < 12; k16++) {
            int poff  = (k16 < 4) ? k16*32 : (k16 < 8) ? 128 + (k16-4)*32 : (k16-8)*32;
            int vbase = (k16 < 4) ? k16*16 : (k16 < 8) ? (k16-4)*16 : 64 + (k16-8)*16;
            uint32_t afr[4];
            ldsm4(afr, sb + PS_OFF + (wm*16 + (lane & 15))*QPITCH
                       + poff + (lane >> 4)*16);
            uint32_t bfr[2][4];
            #pragma unroll
            for (int ng = 0; ng < 2; ng++)
                ldsm4t(bfr[ng], vb + (vbase + (lane & 7) + ((lane >> 3) & 1)*8)*VPITCH
                                + (wn*32 + ng*16 + (lane >> 4)*8)*2);
            #pragma unroll
            for (int nt = 0; nt < 4; nt++) {
                int ng = nt >> 1, nh = nt & 1;
                mma_bf16(oacc[nt], afr, bfr[ng][nh*2], bfr[ng][nh*2+1]);
            }
        }
    }

    // ---- finalize: O/l, split, store ----
    #pragma unroll
    for (int rr = 0; rr < 2; rr++) {
        float inv = 1.0f / lst[rr];
        int row = rbase + rr*8;
        size_t off0 = base + (size_t)(qt*64 + row)*HD;
        #pragma unroll
        for (int nt = 0; nt < 4; nt++) {
            int hd = wn*32 + nt*8 + 2*(lane & 3);
            __nv_bfloat162 h2, l2;
            split2(oacc[nt][rr*2]*inv, oacc[nt][rr*2+1]*inv, h2, l2);
            *(__nv_bfloat162*)(g_Oh + off0 + hd) = h2;
            *(__nv_bfloat162*)(g_Ol + off0 + hd) = l2;
        }
    }
}

// ---------------------------------------------------------------------------
extern "C" void kernel_launch(void* const* d_in, const int* in_sizes, int n_in,
                              void* d_out, int out_size)
{
    const float* x    = (const float*)d_in[0];
    const float* Wqkv = (const float*)d_in[1];
    const float* bqkv = (const float*)d_in[2];
    const float* Wo   = (const float*)d_in[3];
    const float* bo   = (const float*)d_in[4];
    float* out = (float*)d_out;

    cudaFuncSetAttribute(gemm_ext_kernel,
                         cudaFuncAttributeMaxDynamicSharedMemorySize, SMEM_GEMM);
    cudaFuncSetAttribute(attn_kernel,
                         cudaFuncAttributeMaxDynamicSharedMemorySize, SMEM_ATTN);

    __nv_bfloat16 *Xh, *Xl, *WqTh, *WqTl, *WoTh, *WoTl, *Oh, *Ol;
    cudaGetSymbolAddress((void**)&Xh,   g_Xh);
    cudaGetSymbolAddress((void**)&Xl,   g_Xl);
    cudaGetSymbolAddress((void**)&WqTh, g_WqTh);
    cudaGetSymbolAddress((void**)&WqTl, g_WqTl);
    cudaGetSymbolAddress((void**)&WoTh, g_WoTh);
    cudaGetSymbolAddress((void**)&WoTl, g_WoTl);
    cudaGetSymbolAddress((void**)&Oh,   g_Oh);
    cudaGetSymbolAddress((void**)&Ol,   g_Ol);

    split_x_kernel<<<MTOT*DD/1024, 256>>>(x);
    transpose_split_kernel<<<dim3(NQKV/32, DD/32), dim3(32, 8)>>>(Wqkv, DD, NQKV, WqTh, WqTl);
    transpose_split_kernel<<<dim3(DD/32, DD/32), dim3(32, 8)>>>(Wo, DD, DD, WoTh, WoTl);

    gemm_ext_kernel<<<dim3(NQKV/256, MTOT/256), 512, SMEM_GEMM>>>(
        Xh, Xl, WqTh, WqTl, bqkv, nullptr, 0);

    attn_kernel<<<dim3(SS/64, NHEADS), 256, SMEM_ATTN>>>();

    gemm_ext_kernel<<<dim3(DD/256, MTOT/256), 512, SMEM_GEMM>>>(
        Oh, Ol, WoTh, WoTl, bo, out, 1);
}

// round 8
// speedup vs baseline: 2.0734x; 2.0734x over previous
#include <cuda_runtime.h>
#include <cuda_bf16.h>
#include <cstdint>
#include <math.h>

// Problem constants
#define BB 4
#define SS 2048
#define DD 1024
#define HH 16
#define HD 64
#define MTOT (BB*SS)      // 8192
#define NQKV (3*DD)       // 3072
#define NHEADS (BB*HH)    // 64

// Q pre-scale: 1/sqrt(64) * log2(e)  (softmax done in exp2 domain)
#define QSCALE 0.1803368801111204f

// ---------------------------------------------------------------------------
// Scratch (static device globals — allowed)
// ---------------------------------------------------------------------------
__device__ __nv_bfloat16 g_Xh[(size_t)MTOT*DD];
__device__ __nv_bfloat16 g_Xl[(size_t)MTOT*DD];
__device__ __nv_bfloat16 g_WqTh[(size_t)NQKV*DD];
__device__ __nv_bfloat16 g_WqTl[(size_t)NQKV*DD];
__device__ __nv_bfloat16 g_WoTh[(size_t)DD*DD];
__device__ __nv_bfloat16 g_WoTl[(size_t)DD*DD];
__device__ __nv_bfloat16 g_Qh[(size_t)NHEADS*SS*HD];
__device__ __nv_bfloat16 g_Ql[(size_t)NHEADS*SS*HD];
__device__ __nv_bfloat16 g_Kh[(size_t)NHEADS*SS*HD];
__device__ __nv_bfloat16 g_Kl[(size_t)NHEADS*SS*HD];
__device__ __nv_bfloat16 g_Vh[(size_t)NHEADS*SS*HD];
__device__ __nv_bfloat16 g_Vl[(size_t)NHEADS*SS*HD];
__device__ __nv_bfloat16 g_Oh[(size_t)MTOT*DD];
__device__ __nv_bfloat16 g_Ol[(size_t)MTOT*DD];

// ---------------------------------------------------------------------------
// PTX helpers (plain compute_103-compatible: mma.sync / ldmatrix / cp.async)
// ---------------------------------------------------------------------------
__device__ __forceinline__ uint32_t smem_u32(const void* p) {
    uint32_t a;
    asm("{ .reg .u64 t; cvta.to.shared.u64 t, %1; cvt.u32.u64 %0, t; }"
        : "=r"(a) : "l"(p));
    return a;
}
__device__ __forceinline__ void cp16(uint32_t dst, const void* src) {
    asm volatile("cp.async.cg.shared.global [%0], [%1], 16;\n"
                 :: "r"(dst), "l"(src));
}
#define CP_COMMIT() asm volatile("cp.async.commit_group;\n" ::: "memory")
#define CP_WAIT(n)  asm volatile("cp.async.wait_group %0;\n" :: "n"(n) : "memory")

__device__ __forceinline__ void ldsm4(uint32_t* r, uint32_t addr) {
    asm volatile("ldmatrix.sync.aligned.m8n8.x4.shared.b16 {%0,%1,%2,%3}, [%4];\n"
                 : "=r"(r[0]), "=r"(r[1]), "=r"(r[2]), "=r"(r[3]) : "r"(addr));
}
__device__ __forceinline__ void ldsm4t(uint32_t* r, uint32_t addr) {
    asm volatile("ldmatrix.sync.aligned.m8n8.x4.trans.shared.b16 {%0,%1,%2,%3}, [%4];\n"
                 : "=r"(r[0]), "=r"(r[1]), "=r"(r[2]), "=r"(r[3]) : "r"(addr));
}
__device__ __forceinline__ void mma_bf16(float* c, const uint32_t* a,
                                         uint32_t b0, uint32_t b1) {
    asm volatile(
        "mma.sync.aligned.m16n8k16.row.col.f32.bf16.bf16.f32 "
        "{%0,%1,%2,%3}, {%4,%5,%6,%7}, {%8,%9}, {%0,%1,%2,%3};\n"
        : "+f"(c[0]), "+f"(c[1]), "+f"(c[2]), "+f"(c[3])
        : "r"(a[0]), "r"(a[1]), "r"(a[2]), "r"(a[3]), "r"(b0), "r"(b1));
}
__device__ __forceinline__ float ex2(float x) {
    float y;
    asm("ex2.approx.ftz.f32 %0, %1;" : "=f"(y) : "f"(x));
    return y;
}
__device__ __forceinline__ void split2(float x, float y,
                                       __nv_bfloat162& h2, __nv_bfloat162& l2) {
    __nv_bfloat16 hx = __float2bfloat16(x);
    __nv_bfloat16 hy = __float2bfloat16(y);
    h2.x = hx; h2.y = hy;
    l2.x = __float2bfloat16(x - __bfloat162float(hx));
    l2.y = __float2bfloat16(y - __bfloat162float(hy));
}

// ---------------------------------------------------------------------------
// Prep: split x into bf16 hi/lo
// ---------------------------------------------------------------------------
__global__ void __launch_bounds__(256) split_x_kernel(const float* __restrict__ x)
{
    size_t i4 = ((size_t)blockIdx.x * 256 + threadIdx.x) * 4;
    float4 v = *(const float4*)(x + i4);
    __nv_bfloat162 h0, l0, h1, l1;
    split2(v.x, v.y, h0, l0);
    split2(v.z, v.w, h1, l1);
    *(__nv_bfloat162*)(g_Xh + i4)     = h0;
    *(__nv_bfloat162*)(g_Xh + i4 + 2) = h1;
    *(__nv_bfloat162*)(g_Xl + i4)     = l0;
    *(__nv_bfloat162*)(g_Xl + i4 + 2) = l1;
}

// Prep: transpose W [K][N] -> T[n][k] bf16 hi/lo
__global__ void __launch_bounds__(256) transpose_split_kernel(
    const float* __restrict__ W, int K, int N,
    __nv_bfloat16* __restrict__ Th, __nv_bfloat16* __restrict__ Tl)
{
    __shared__ float t[32][33];
    int nb = blockIdx.x * 32, kb = blockIdx.y * 32;
    int tx = threadIdx.x, ty = threadIdx.y;
    #pragma unroll
    for (int j = 0; j < 4; j++)
        t[ty + j*8][tx] = W[(size_t)(kb + ty + j*8) * N + nb + tx];
    __syncthreads();
    #pragma unroll
    for (int j = 0; j < 4; j++) {
        int n = nb + ty + j*8;
        float v = t[tx][ty + j*8];
        __nv_bfloat16 h = __float2bfloat16(v);
        Th[(size_t)n * K + kb + tx] = h;
        Tl[(size_t)n * K + kb + tx] = __float2bfloat16(v - __bfloat162float(h));
    }
}

// ---------------------------------------------------------------------------
// Extended-K bf16 GEMM (3-pass split as K=3072):
//   C[M][N] = sum_p  Ap . Bp^T   with A pattern [h|l|h], B pattern [h|h|l]
// BM=BN=128, BK=64 per stage, 256 threads, 8 warps (2m x 4n),
// 3-stage cp.async (110.6KB smem), 2 CTAs/SM.
// Register-level software pipeline: A fragments double-buffered (prefetch
// slab s+1 during slab s MMAs); B half 1 loaded between slabs 1 and 2.
// Reg budget: acc 64 + A 32 + B 16 = 112 <= 128 cap.
// ---------------------------------------------------------------------------
#define GPITCH 144
#define GSTG (128*GPITCH)   // 18432 per operand per stage
#define SMEM_GEMM (6*GSTG)  // 110592

__global__ void __launch_bounds__(256, 2) gemm_ext_kernel(
    const __nv_bfloat16* __restrict__ Ah, const __nv_bfloat16* __restrict__ Al,
    const __nv_bfloat16* __restrict__ Bh, const __nv_bfloat16* __restrict__ Bl,
    const float* __restrict__ bias, float* __restrict__ out, int mode)
{
    extern __shared__ char sm[];
    const uint32_t sb = smem_u32(sm);
    const int tid = threadIdx.x, wid = tid >> 5, lane = tid & 31;
    const int wm = wid >> 2, wn = wid & 3;   // 2 x 4 warp grid
    const int m0 = blockIdx.y * 128, n0 = blockIdx.x * 128;

    float acc[4][4][4];
    #pragma unroll
    for (int i = 0; i < 4; i++)
        #pragma unroll
        for (int j = 0; j < 4; j++)
            #pragma unroll
            for (int e = 0; e < 4; e++) acc[i][j][e] = 0.0f;

    // issue one 64-K chunk into stage st (0..2): 4 A + 4 B cp16 per thread
    #define GEMM_ISSUE(c, st) do {                                             \
        int _p = (c) >> 4; int _kb = ((c) & 15) * 64;                          \
        const __nv_bfloat16* _Ap = (_p == 1) ? Al : Ah;                        \
        const __nv_bfloat16* _Bp = (_p == 2) ? Bl : Bh;                        \
        uint32_t _da = sb + (st) * GSTG;                                       \
        uint32_t _db = sb + 3*GSTG + (st) * GSTG;                              \
        _Pragma("unroll")                                                      \
        for (int _j = 0; _j < 4; _j++) {                                       \
            int _idx = tid + _j*256;                                           \
            int _row = _idx >> 3, _q = _idx & 7;                               \
            cp16(_da + _row*GPITCH + _q*16,                                    \
                 _Ap + (size_t)(m0+_row)*DD + _kb + _q*8);                     \
            cp16(_db + _row*GPITCH + _q*16,                                    \
                 _Bp + (size_t)(n0+_row)*DD + _kb + _q*8);                     \
        }                                                                      \
    } while (0)

    GEMM_ISSUE(0, 0); CP_COMMIT();
    GEMM_ISSUE(1, 1); CP_COMMIT();

    const int NCH = 48;  // 3072 / 64
    int cur = 0;         // stage of chunk c
    for (int c = 0; c < NCH; c++) {
        CP_WAIT(1);
        __syncthreads();
        int nxt = cur + 2 >= 3 ? cur - 1 : cur + 2;
        if (c + 2 < NCH) GEMM_ISSUE(c + 2, nxt);
        CP_COMMIT();

        uint32_t da = sb + cur * GSTG;
        uint32_t db = sb + 3*GSTG + cur * GSTG;

        // slabs s = 0..3: kc2 = s>>1 (64B column half), kk = s&1 (k16 slab)
        uint32_t bfr[4][4];     // B: n8 x k32 fragments for current kc2
        uint32_t afr[2][4][4];  // A: double-buffered m16 x k16 fragments

        #define LDB(kc2) do {                                                  \
            _Pragma("unroll")                                                  \
            for (int _nt = 0; _nt < 4; _nt++)                                  \
                ldsm4(bfr[_nt], db + (wn*32 + _nt*8 + (lane & 7))*GPITCH       \
                               + (kc2)*64 + (lane >> 3)*16);                   \
        } while (0)
        #define LDA(s) do {                                                    \
            _Pragma("unroll")                                                  \
            for (int _mt = 0; _mt < 4; _mt++)                                  \
                ldsm4(afr[(s) & 1][_mt],                                       \
                      da + (wm*64 + _mt*16 + (lane & 15))*GPITCH               \
                      + ((s) >> 1)*64 + ((s) & 1)*32 + (lane >> 4)*16);        \
        } while (0)

        LDB(0);
        LDA(0);
        #pragma unroll
        for (int s = 0; s < 4; s++) {
            if (s < 3) LDA(s + 1);           // prefetch next A slab
            #pragma unroll
            for (int mt = 0; mt < 4; mt++)
                #pragma unroll
                for (int nt = 0; nt < 4; nt++)
                    mma_bf16(acc[mt][nt], afr[s & 1][mt],
                             bfr[nt][(s & 1)*2], bfr[nt][(s & 1)*2 + 1]);
            if (s == 1) LDB(1);              // load B for second column half
        }
        #undef LDB
        #undef LDA
        cur = cur + 1 >= 3 ? 0 : cur + 1;
    }

    // ---- epilogue ----
    #pragma unroll
    for (int mt = 0; mt < 4; mt++) {
        #pragma unroll
        for (int rr = 0; rr < 2; rr++) {
            int row = wm*64 + mt*16 + (lane >> 2) + rr*8;
            int m = m0 + row;
            #pragma unroll
            for (int nt = 0; nt < 4; nt++) {
                int col = n0 + wn*32 + nt*8 + 2*(lane & 3);
                float v0 = acc[mt][nt][rr*2]   + bias[col];
                float v1 = acc[mt][nt][rr*2+1] + bias[col+1];
                if (mode == 1) {
                    float2 f2; f2.x = v0; f2.y = v1;
                    *(float2*)&out[(size_t)m*DD + col] = f2;
                } else {
                    int h = col / 192;
                    int t = col - h*192;
                    int which = t >> 6;
                    int hd = t & 63;
                    if (which == 0) { v0 *= QSCALE; v1 *= QSCALE; }
                    __nv_bfloat162 h2, l2;
                    split2(v0, v1, h2, l2);
                    int b = m >> 11, s = m & 2047;
                    size_t off = (((size_t)b*HH + h)*SS + s)*HD + hd;
                    __nv_bfloat16* dh = (which == 0) ? g_Qh : (which == 1) ? g_Kh : g_Vh;
                    __nv_bfloat16* dl = (which == 0) ? g_Ql : (which == 1) ? g_Kl : g_Vl;
                    *(__nv_bfloat162*)(dh + off) = h2;
                    *(__nv_bfloat162*)(dl + off) = l2;
                }
            }
        }
    }
}

// ---------------------------------------------------------------------------
// Flash attention via mma.sync, 3-pass split, physical hi/lo dedup (as R6).
// ---------------------------------------------------------------------------
#define QPITCH 272
#define VPITCH 144
#define QS_OFF 0
#define KS_OFF 17408                 // Q: 64*272
#define KBUF   17408                 // K buf: 64*272
#define VS_OFF (KS_OFF + 2*KBUF)     // 52224
#define VBUF   18432                 // V buf: 128*144
#define PS_OFF (VS_OFF + 2*VBUF)     // 89088
#define RED_OFF (PS_OFF + 17408)     // 106496
#define SMEM_ATTN (RED_OFF + 1024)   // 107520

__global__ void __launch_bounds__(256, 2) attn_kernel()
{
    const int qt = blockIdx.x;   // 0..31
    const int bh = blockIdx.y;   // 0..63
    extern __shared__ char sm[];
    const uint32_t sb = smem_u32(sm);
    const int tid = threadIdx.x, wid = tid >> 5, lane = tid & 31;
    const int wm = wid >> 1, wn = wid & 1;

    const size_t base = (size_t)bh * SS * HD;
    const __nv_bfloat16* Qh = g_Qh + base + (size_t)qt*64*HD;
    const __nv_bfloat16* Ql = g_Ql + base + (size_t)qt*64*HD;
    const __nv_bfloat16* Kh = g_Kh + base;
    const __nv_bfloat16* Kl = g_Kl + base;
    const __nv_bfloat16* Vh = g_Vh + base;
    const __nv_bfloat16* Vl = g_Vl + base;

    // ---- load Q: phys [Qh(128B) | Ql(128B)] per row ----
    #pragma unroll
    for (int j = 0; j < 4; j++) {
        int idx = tid + j*256;
        int row = idx >> 4, q = idx & 15;
        if (q < 8)
            cp16(sb + QS_OFF + row*QPITCH + q*16, Qh + (size_t)row*HD + q*8);
        else
            cp16(sb + QS_OFF + row*QPITCH + 128 + (q-8)*16, Ql + (size_t)row*HD + (q-8)*8);
    }

    // K/V tile loader: K phys [Kh|Kl] 272B pitch; V phys [Vh rows 0-63; Vl rows 64-127]
    #define LOAD_KV(t, buf) do {                                               \
        int _s0 = (t) * 64;                                                    \
        _Pragma("unroll")                                                      \
        for (int j = 0; j < 4; j++) {                                          \
            int _idx = tid + j*256;                                            \
            int _row = _idx >> 4, _q = _idx & 15;                              \
            if (_q < 8)                                                        \
                cp16(sb + KS_OFF + (buf)*KBUF + _row*QPITCH + _q*16,           \
                     Kh + (size_t)(_s0 + _row)*HD + _q*8);                     \
            else                                                               \
                cp16(sb + KS_OFF + (buf)*KBUF + _row*QPITCH + 128 + (_q-8)*16, \
                     Kl + (size_t)(_s0 + _row)*HD + (_q-8)*8);                 \
        }                                                                      \
        _Pragma("unroll")                                                      \
        for (int j = 0; j < 4; j++) {                                          \
            int _idx = tid + j*256;                                            \
            int _vr = _idx >> 3, _q = _idx & 7;                                \
            const __nv_bfloat16* _src = (_vr < 64)                             \
                ? Vh + (size_t)(_s0 + _vr)*HD + _q*8                           \
                : Vl + (size_t)(_s0 + _vr - 64)*HD + _q*8;                     \
            cp16(sb + VS_OFF + (buf)*VBUF + _vr*VPITCH + _q*16, _src);         \
        }                                                                      \
    } while (0)

    LOAD_KV(0, 0);
    CP_COMMIT();

    float oacc[4][4];
    #pragma unroll
    for (int j = 0; j < 4; j++)
        #pragma unroll
        for (int e = 0; e < 4; e++) oacc[j][e] = 0.0f;
    float mst[2] = {-1e30f, -1e30f};
    float lst[2] = {0.0f, 0.0f};

    float* redm = (float*)(sm + RED_OFF);   // [2][64]
    float* reds = redm + 128;               // [2][64]
    const int rbase = wm*16 + (lane >> 2);

    // pass index maps (byte offsets within 272B rows); each kc = 32 ext-K
    const int qoff_tab[6] = {0, 64, 128, 192, 0, 64};     // Q: [h|l|h]
    const int koff_tab[6] = {0, 64, 0, 64, 128, 192};     // K: [h|h|l]

    for (int t = 0; t < 32; t++) {
        const int buf = t & 1;
        CP_WAIT(0);                            // tile t fully arrived
        __syncthreads();                       // + all warps past PV(t-1)
        if (t + 1 < 32) LOAD_KV(t + 1, buf ^ 1);
        CP_COMMIT();

        // ---- S = Q_ext . K_ext^T (64 x 64, ext K = 192) ----
        float sacc[4][4];
        #pragma unroll
        for (int j = 0; j < 4; j++)
            #pragma unroll
            for (int e = 0; e < 4; e++) sacc[j][e] = 0.0f;

        const uint32_t kb = sb + KS_OFF + buf*KBUF;
        #pragma unroll
        for (int kc = 0; kc < 6; kc++) {
            uint32_t bfr[4][4];
            #pragma unroll
            for (int nt = 0; nt < 4; nt++)
                ldsm4(bfr[nt], kb + (wn*32 + nt*8 + (lane & 7))*QPITCH
                               + koff_tab[kc] + (lane >> 3)*16);
            #pragma unroll
            for (int kk = 0; kk < 2; kk++) {
                uint32_t afr[4];
                ldsm4(afr, sb + QS_OFF + (wm*16 + (lane & 15))*QPITCH
                           + qoff_tab[kc] + kk*32 + (lane >> 4)*16);
                #pragma unroll
                for (int nt = 0; nt < 4; nt++)
                    mma_bf16(sacc[nt], afr, bfr[nt][kk*2], bfr[nt][kk*2+1]);
            }
        }

        // ---- online softmax (exp2 domain) ----
        #pragma unroll
        for (int rr = 0; rr < 2; rr++) {
            float mx = sacc[0][rr*2];
            #pragma unroll
            for (int nt = 0; nt < 4; nt++) {
                mx = fmaxf(mx, sacc[nt][rr*2]);
                mx = fmaxf(mx, sacc[nt][rr*2+1]);
            }
            mx = fmaxf(mx, __shfl_xor_sync(0xffffffffu, mx, 1));
            mx = fmaxf(mx, __shfl_xor_sync(0xffffffffu, mx, 2));
            if ((lane & 3) == 0)
                redm[wn*64 + rbase + rr*8] = mx;
        }
        __syncthreads();

        float alpha[2];
        #pragma unroll
        for (int rr = 0; rr < 2; rr++) {
            int row = rbase + rr*8;
            float rm = fmaxf(redm[row], redm[64 + row]);
            float mn = fmaxf(mst[rr], rm);
            alpha[rr] = ex2(mst[rr] - mn);
            mst[rr] = mn;
            float sum = 0.0f;
            #pragma unroll
            for (int nt = 0; nt < 4; nt++) {
                float p0 = ex2(sacc[nt][rr*2]   - mn);
                float p1 = ex2(sacc[nt][rr*2+1] - mn);
                sacc[nt][rr*2] = p0; sacc[nt][rr*2+1] = p1;
                sum += p0 + p1;
            }
            sum += __shfl_xor_sync(0xffffffffu, sum, 1);
            sum += __shfl_xor_sync(0xffffffffu, sum, 2);
            if ((lane & 3) == 0)
                reds[wn*64 + row] = sum;
        }

        // write P phys [Ph(128B) | Pl(128B)]
        #pragma unroll
        for (int rr = 0; rr < 2; rr++) {
            int row = rbase + rr*8;
            char* prow = sm + PS_OFF + row*QPITCH;
            #pragma unroll
            for (int nt = 0; nt < 4; nt++) {
                int klc = wn*32 + nt*8 + 2*(lane & 3);
                __nv_bfloat162 h2, l2;
                split2(sacc[nt][rr*2], sacc[nt][rr*2+1], h2, l2);
                *(__nv_bfloat162*)(prow + klc*2)       = h2;
                *(__nv_bfloat162*)(prow + 128 + klc*2) = l2;
            }
        }
        __syncthreads();

        // l update + O rescale
        #pragma unroll
        for (int rr = 0; rr < 2; rr++) {
            int row = rbase + rr*8;
            lst[rr] = lst[rr]*alpha[rr] + reds[row] + reds[64+row];
            #pragma unroll
            for (int nt = 0; nt < 4; nt++) {
                oacc[nt][rr*2]   *= alpha[rr];
                oacc[nt][rr*2+1] *= alpha[rr];
            }
        }

        // ---- O += P_ext . V_ext (ext K = 192 over keys) ----
        // passes: k16 0-3: Ph.Vh | 4-7: Pl.Vh | 8-11: Ph.Vl
        const uint32_t vb = sb + VS_OFF + buf*VBUF;
        #pragma unroll
        for (int k16 = 0; k16 < 12; k16++) {
            int poff  = (k16 < 4) ? k16*32 : (k16 < 8) ? 128 + (k16-4)*32 : (k16-8)*32;
            int vbase = (k16 < 4) ? k16*16 : (k16 < 8) ? (k16-4)*16 : 64 + (k16-8)*16;
            uint32_t afr[4];
            ldsm4(afr, sb + PS_OFF + (wm*16 + (lane & 15))*QPITCH
                       + poff + (lane >> 4)*16);
            uint32_t bfr[2][4];
            #pragma unroll
            for (int ng = 0; ng < 2; ng++)
                ldsm4t(bfr[ng], vb + (vbase + (lane & 7) + ((lane >> 3) & 1)*8)*VPITCH
                                + (wn*32 + ng*16 + (lane >> 4)*8)*2);
            #pragma unroll
            for (int nt = 0; nt < 4; nt++) {
                int ng = nt >> 1, nh = nt & 1;
                mma_bf16(oacc[nt], afr, bfr[ng][nh*2], bfr[ng][nh*2+1]);
            }
        }
    }

    // ---- finalize: O/l, split, store ----
    #pragma unroll
    for (int rr = 0; rr < 2; rr++) {
        float inv = 1.0f / lst[rr];
        int row = rbase + rr*8;
        size_t off0 = base + (size_t)(qt*64 + row)*HD;
        #pragma unroll
        for (int nt = 0; nt < 4; nt++) {
            int hd = wn*32 + nt*8 + 2*(lane & 3);
            __nv_bfloat162 h2, l2;
            split2(oacc[nt][rr*2]*inv, oacc[nt][rr*2+1]*inv, h2, l2);
            *(__nv_bfloat162*)(g_Oh + off0 + hd) = h2;
            *(__nv_bfloat162*)(g_Ol + off0 + hd) = l2;
        }
    }
}

// ---------------------------------------------------------------------------
extern "C" void kernel_launch(void* const* d_in, const int* in_sizes, int n_in,
                              void* d_out, int out_size)
{
    const float* x    = (const float*)d_in[0];
    const float* Wqkv = (const float*)d_in[1];
    const float* bqkv = (const float*)d_in[2];
    const float* Wo   = (const float*)d_in[3];
    const float* bo   = (const float*)d_in[4];
    float* out = (float*)d_out;

    cudaFuncSetAttribute(gemm_ext_kernel,
                         cudaFuncAttributeMaxDynamicSharedMemorySize, SMEM_GEMM);
    cudaFuncSetAttribute(attn_kernel,
                         cudaFuncAttributeMaxDynamicSharedMemorySize, SMEM_ATTN);

    __nv_bfloat16 *Xh, *Xl, *WqTh, *WqTl, *WoTh, *WoTl, *Oh, *Ol;
    cudaGetSymbolAddress((void**)&Xh,   g_Xh);
    cudaGetSymbolAddress((void**)&Xl,   g_Xl);
    cudaGetSymbolAddress((void**)&WqTh, g_WqTh);
    cudaGetSymbolAddress((void**)&WqTl, g_WqTl);
    cudaGetSymbolAddress((void**)&WoTh, g_WoTh);
    cudaGetSymbolAddress((void**)&WoTl, g_WoTl);
    cudaGetSymbolAddress((void**)&Oh,   g_Oh);
    cudaGetSymbolAddress((void**)&Ol,   g_Ol);

    split_x_kernel<<<MTOT*DD/1024, 256>>>(x);
    transpose_split_kernel<<<dim3(NQKV/32, DD/32), dim3(32, 8)>>>(Wqkv, DD, NQKV, WqTh, WqTl);
    transpose_split_kernel<<<dim3(DD/32, DD/32), dim3(32, 8)>>>(Wo, DD, DD, WoTh, WoTl);

    gemm_ext_kernel<<<dim3(NQKV/128, MTOT/128), 256, SMEM_GEMM>>>(
        Xh, Xl, WqTh, WqTl, bqkv, nullptr, 0);

    attn_kernel<<<dim3(SS/64, NHEADS), 256, SMEM_ATTN>>>();

    gemm_ext_kernel<<<dim3(DD/128, MTOT/128), 256, SMEM_GEMM>>>(
        Oh, Ol, WoTh, WoTl, bo, out, 1);
}